// round 2
// baseline (speedup 1.0000x reference)
#include <cuda_runtime.h>
#include <cuda_bf16.h>
#include <math.h>

#define NN 20000
#define EE 320000

// ---------------- scratch (device globals; no allocations allowed) ----------
__device__ __align__(256) float g_fs[NN * 512];
__device__ __align__(256) float g_fd[NN * 512];
__device__ __align__(256) float g_hin[NN * 128];
__device__ __align__(256) float g_logit[EE * 4];
__device__ __align__(256) int   g_deg[NN];
__device__ __align__(256) int   g_rowptr[NN + 1];
__device__ __align__(256) int   g_cursor[NN];
__device__ __align__(256) int   g_csr_eid[EE];
__device__ __align__(256) int   g_csr_src[EE];

// ---------------- CSR build --------------------------------------------------
__global__ void zero_deg_kernel(int n) {
    int i = blockIdx.x * blockDim.x + threadIdx.x;
    if (i < n) g_deg[i] = 0;
}

__global__ void hist_dst_kernel(const int* __restrict__ dst, int E) {
    int i = blockIdx.x * blockDim.x + threadIdx.x;
    if (i < E) atomicAdd(&g_deg[dst[i]], 1);
}

// single-block exclusive scan of g_deg -> g_rowptr (and g_cursor copy)
__global__ void scan_exclusive_kernel(int n) {
    __shared__ int wsum[32];
    __shared__ int carry_s;
    int tid = threadIdx.x, lane = tid & 31, wid = tid >> 5;
    if (tid == 0) carry_s = 0;
    __syncthreads();
    for (int base = 0; base < n; base += blockDim.x) {
        int i = base + tid;
        int v = (i < n) ? g_deg[i] : 0;
        int x = v;
        #pragma unroll
        for (int o = 1; o < 32; o <<= 1) {
            int y = __shfl_up_sync(0xffffffffu, x, o);
            if (lane >= o) x += y;
        }
        if (lane == 31) wsum[wid] = x;
        __syncthreads();
        if (wid == 0) {
            int s = wsum[lane];
            #pragma unroll
            for (int o = 1; o < 32; o <<= 1) {
                int y = __shfl_up_sync(0xffffffffu, s, o);
                if (lane >= o) s += y;
            }
            wsum[lane] = s;
        }
        __syncthreads();
        int incl = x + (wid > 0 ? wsum[wid - 1] : 0) + carry_s;
        if (i < n) {
            g_rowptr[i] = incl - v;
            g_cursor[i] = incl - v;
        }
        __syncthreads();
        if (tid == blockDim.x - 1) carry_s = incl;
        __syncthreads();
    }
    if (tid == 0) g_rowptr[n] = carry_s;
}

__global__ void scatter_csr_kernel(const int* __restrict__ src,
                                   const int* __restrict__ dst, int E) {
    int i = blockIdx.x * blockDim.x + threadIdx.x;
    if (i < E) {
        int p = atomicAdd(&g_cursor[dst[i]], 1);
        g_csr_eid[p] = i;
        g_csr_src[p] = src[i];
    }
}

// ---------------- SGEMM: C[MxN] = A[MxK] * B[KxN], row-major, fp32 -----------
// 128x128 block tile, BK=8, 256 threads, 8x8 microtile.
__global__ void __launch_bounds__(256)
sgemm128_kernel(const float* __restrict__ A, const float* __restrict__ B,
                float* __restrict__ C, int M, int N, int K) {
    __shared__ float As[8][128];
    __shared__ float Bs[8][128];
    int tid = threadIdx.x;
    int rowBase = blockIdx.y * 128;
    int colBase = blockIdx.x * 128;
    int tx = tid & 15;        // 0..15 -> 8 cols each
    int ty = tid >> 4;        // 0..15 -> 8 rows each
    int aRow = tid >> 1;      // 0..127
    int aCol = (tid & 1) * 4; // 0 or 4
    int bRow = tid >> 5;      // 0..7
    int bCol = (tid & 31) * 4;

    float acc[8][8];
    #pragma unroll
    for (int i = 0; i < 8; i++)
        #pragma unroll
        for (int j = 0; j < 8; j++) acc[i][j] = 0.f;

    for (int k0 = 0; k0 < K; k0 += 8) {
        float4 av = make_float4(0.f, 0.f, 0.f, 0.f);
        int ar = rowBase + aRow;
        if (ar < M) av = *(const float4*)(A + (size_t)ar * K + k0 + aCol);
        As[aCol + 0][aRow] = av.x;
        As[aCol + 1][aRow] = av.y;
        As[aCol + 2][aRow] = av.z;
        As[aCol + 3][aRow] = av.w;
        float4 bv = *(const float4*)(B + (size_t)(k0 + bRow) * N + colBase + bCol);
        *(float4*)&Bs[bRow][bCol] = bv;
        __syncthreads();
        #pragma unroll
        for (int k = 0; k < 8; k++) {
            float4 a0 = *(float4*)&As[k][ty * 8];
            float4 a1 = *(float4*)&As[k][ty * 8 + 4];
            float4 b0 = *(float4*)&Bs[k][tx * 8];
            float4 b1 = *(float4*)&Bs[k][tx * 8 + 4];
            float ra[8] = {a0.x, a0.y, a0.z, a0.w, a1.x, a1.y, a1.z, a1.w};
            float rb[8] = {b0.x, b0.y, b0.z, b0.w, b1.x, b1.y, b1.z, b1.w};
            #pragma unroll
            for (int i = 0; i < 8; i++)
                #pragma unroll
                for (int j = 0; j < 8; j++) acc[i][j] += ra[i] * rb[j];
        }
        __syncthreads();
    }

    #pragma unroll
    for (int i = 0; i < 8; i++) {
        int r = rowBase + ty * 8 + i;
        if (r >= M) break;
        float4* cp = (float4*)(C + (size_t)r * N + colBase + tx * 8);
        cp[0] = make_float4(acc[i][0], acc[i][1], acc[i][2], acc[i][3]);
        cp[1] = make_float4(acc[i][4], acc[i][5], acc[i][6], acc[i][7]);
    }
}

// ---------------- edge logits: warp per edge --------------------------------
// logit[e,h] = sum_d attn[h,d] * leaky_relu(fs[src,h,d] + fd[dst,h,d], 0.2)
__global__ void __launch_bounds__(256)
edge_logit_kernel(const float* __restrict__ fs, const float* __restrict__ fd,
                  const float* __restrict__ attn, const int* __restrict__ src,
                  const int* __restrict__ dst, int E, int D) {
    int gw = (blockIdx.x * blockDim.x + threadIdx.x) >> 5;
    int lane = threadIdx.x & 31;
    if (gw >= E) return;
    int HD = 4 * D;
    const float* ps = fs + (size_t)src[gw] * HD;
    const float* pd = fd + (size_t)dst[gw] * HD;
    float lg[4];
    #pragma unroll
    for (int h = 0; h < 4; h++) {
        float acc = 0.f;
        if (D == 128) {
            int o = h * 128 + lane * 4;
            float4 a = *(const float4*)(ps + o);
            float4 b = *(const float4*)(pd + o);
            float4 w = *(const float4*)(attn + o);
            float x;
            x = a.x + b.x; acc += w.x * (x > 0.f ? x : 0.2f * x);
            x = a.y + b.y; acc += w.y * (x > 0.f ? x : 0.2f * x);
            x = a.z + b.z; acc += w.z * (x > 0.f ? x : 0.2f * x);
            x = a.w + b.w; acc += w.w * (x > 0.f ? x : 0.2f * x);
        } else { // D == 64
            int o = h * 64 + lane * 2;
            float2 a = *(const float2*)(ps + o);
            float2 b = *(const float2*)(pd + o);
            float2 w = *(const float2*)(attn + o);
            float x;
            x = a.x + b.x; acc += w.x * (x > 0.f ? x : 0.2f * x);
            x = a.y + b.y; acc += w.y * (x > 0.f ? x : 0.2f * x);
        }
        #pragma unroll
        for (int o = 16; o; o >>= 1) acc += __shfl_xor_sync(0xffffffffu, acc, o);
        lg[h] = acc;
    }
    if (lane == 0) {
        *(float4*)(g_logit + (size_t)gw * 4) = make_float4(lg[0], lg[1], lg[2], lg[3]);
    }
}

// ---------------- per-node softmax + aggregation + head-mean + leaky --------
// block = 128 threads (warp w = head w); one block per dst node.
__global__ void __launch_bounds__(128)
gat_agg_kernel(const float* __restrict__ fs, const float* __restrict__ b,
               float* __restrict__ hout, int D) {
    __shared__ float sh[512];
    int v = blockIdx.x;
    int lane = threadIdx.x & 31;
    int w = threadIdx.x >> 5;   // head id
    int HD = 4 * D;
    int e0 = g_rowptr[v], e1 = g_rowptr[v + 1];

    // per-head max over in-edges
    float mx = -INFINITY;
    for (int e = e0 + lane; e < e1; e += 32)
        mx = fmaxf(mx, g_logit[(size_t)g_csr_eid[e] * 4 + w]);
    #pragma unroll
    for (int o = 16; o; o >>= 1) mx = fmaxf(mx, __shfl_xor_sync(0xffffffffu, mx, o));

    // per-head exp-sum
    float sm = 0.f;
    for (int e = e0 + lane; e < e1; e += 32)
        sm += __expf(g_logit[(size_t)g_csr_eid[e] * 4 + w] - mx);
    #pragma unroll
    for (int o = 16; o; o >>= 1) sm += __shfl_xor_sync(0xffffffffu, sm, o);
    float inv = (e1 > e0) ? 1.f / sm : 0.f;

    // weighted aggregation of fs[src] rows
    float a0 = 0.f, a1 = 0.f, a2 = 0.f, a3 = 0.f;
    if (D == 128) {
        const int off = w * 128 + lane * 4;
        for (int e = e0; e < e1; e++) {
            float alpha = __expf(g_logit[(size_t)g_csr_eid[e] * 4 + w] - mx) * inv;
            float4 t = *(const float4*)(fs + (size_t)g_csr_src[e] * HD + off);
            a0 += alpha * t.x; a1 += alpha * t.y; a2 += alpha * t.z; a3 += alpha * t.w;
        }
        sh[off] = a0; sh[off + 1] = a1; sh[off + 2] = a2; sh[off + 3] = a3;
    } else { // D == 64
        const int off = w * 64 + lane * 2;
        for (int e = e0; e < e1; e++) {
            float alpha = __expf(g_logit[(size_t)g_csr_eid[e] * 4 + w] - mx) * inv;
            float2 t = *(const float2*)(fs + (size_t)g_csr_src[e] * HD + off);
            a0 += alpha * t.x; a1 += alpha * t.y;
        }
        sh[off] = a0; sh[off + 1] = a1;
    }
    __syncthreads();

    // head mean + bias + leaky(0.01)
    if (threadIdx.x < D) {
        int t = threadIdx.x;
        float m = 0.f;
        #pragma unroll
        for (int h = 0; h < 4; h++) m += sh[h * D + t] + b[h * D + t];
        m *= 0.25f;
        hout[(size_t)v * D + t] = (m > 0.f) ? m : 0.01f * m;
    }
}

// ---------------- final node-mean readout -----------------------------------
__global__ void node_mean_kernel(const float* __restrict__ hin,
                                 float* __restrict__ out, int n, int D) {
    int d = blockIdx.x;
    float s = 0.f;
    for (int v = threadIdx.x; v < n; v += blockDim.x)
        s += hin[(size_t)v * D + d];
    __shared__ float red[256];
    red[threadIdx.x] = s;
    __syncthreads();
    for (int o = 128; o; o >>= 1) {
        if (threadIdx.x < o) red[threadIdx.x] += red[threadIdx.x + o];
        __syncthreads();
    }
    if (threadIdx.x == 0) out[d] = red[0] / (float)n;
}

// ---------------- launch ----------------------------------------------------
extern "C" void kernel_launch(void* const* d_in, const int* in_sizes, int n_in,
                              void* d_out, int out_size) {
    const float* n_feat = (const float*)d_in[0];
    const int*   src    = (const int*)d_in[1];
    const int*   dst    = (const int*)d_in[2];
    const float* Wl0 = (const float*)d_in[3];
    const float* Wr0 = (const float*)d_in[4];
    const float* attn0 = (const float*)d_in[5];
    const float* b0 = (const float*)d_in[6];
    const float* Wl1 = (const float*)d_in[7];
    const float* Wr1 = (const float*)d_in[8];
    const float* attn1 = (const float*)d_in[9];
    const float* b1 = (const float*)d_in[10];
    const float* Wl2 = (const float*)d_in[11];
    const float* Wr2 = (const float*)d_in[12];
    const float* attn2 = (const float*)d_in[13];
    const float* b2 = (const float*)d_in[14];
    float* out = (float*)d_out;

    int n = in_sizes[0] / 512;   // 20000
    int E = in_sizes[1];         // 320000

    float *fs, *fd, *hin;
    cudaGetSymbolAddress((void**)&fs, g_fs);
    cudaGetSymbolAddress((void**)&fd, g_fd);
    cudaGetSymbolAddress((void**)&hin, g_hin);

    // CSR by dst (dst is constant input; rebuilt each call, deterministic work)
    zero_deg_kernel<<<(n + 255) / 256, 256>>>(n);
    hist_dst_kernel<<<(E + 255) / 256, 256>>>(dst, E);
    scan_exclusive_kernel<<<1, 1024>>>(n);
    scatter_csr_kernel<<<(E + 255) / 256, 256>>>(src, dst, E);

    dim3 gemmBlk(256);
    int eblocks = (E + 7) / 8; // 8 warps per 256-thread block

    // ---- layer 0: 512 -> 4x128
    {
        dim3 grid(512 / 128, (n + 127) / 128);
        sgemm128_kernel<<<grid, gemmBlk>>>(n_feat, Wl0, fs, n, 512, 512);
        sgemm128_kernel<<<grid, gemmBlk>>>(n_feat, Wr0, fd, n, 512, 512);
        edge_logit_kernel<<<eblocks, 256>>>(fs, fd, attn0, src, dst, E, 128);
        gat_agg_kernel<<<n, 128>>>(fs, b0, hin, 128);
    }
    // ---- layer 1: 128 -> 4x128
    {
        dim3 grid(512 / 128, (n + 127) / 128);
        sgemm128_kernel<<<grid, gemmBlk>>>(hin, Wl1, fs, n, 512, 128);
        sgemm128_kernel<<<grid, gemmBlk>>>(hin, Wr1, fd, n, 512, 128);
        edge_logit_kernel<<<eblocks, 256>>>(fs, fd, attn1, src, dst, E, 128);
        gat_agg_kernel<<<n, 128>>>(fs, b1, hin, 128);
    }
    // ---- layer 2: 128 -> 4x64
    {
        dim3 grid(256 / 128, (n + 127) / 128);
        sgemm128_kernel<<<grid, gemmBlk>>>(hin, Wl2, fs, n, 256, 128);
        sgemm128_kernel<<<grid, gemmBlk>>>(hin, Wr2, fd, n, 256, 128);
        edge_logit_kernel<<<eblocks, 256>>>(fs, fd, attn2, src, dst, E, 64);
        gat_agg_kernel<<<n, 128>>>(fs, b2, hin, 64);
    }

    node_mean_kernel<<<64, 256>>>(hin, out, n, 64);
}

// round 5
// speedup vs baseline: 1.4685x; 1.4685x over previous
#include <cuda_runtime.h>
#include <cuda_bf16.h>
#include <stdint.h>
#include <stddef.h>
#include <math.h>

typedef unsigned int u32;

#define NN 20000
#define EE 320000

// ---------------- scratch (device globals; no allocations allowed) ----------
__device__ __align__(256) float g_fs[NN * 512];
__device__ __align__(256) float g_fd[NN * 512];
__device__ __align__(256) float g_hin[NN * 128];
__device__ __align__(256) float g_logit[EE * 4];
__device__ __align__(256) int   g_deg[NN];
__device__ __align__(256) int   g_rowptr[NN + 1];
__device__ __align__(256) int   g_cursor[NN];
__device__ __align__(256) int   g_csr_eid[EE];
__device__ __align__(256) int   g_csr_src[EE];
// bf16 hi/lo split buffers for tensor-core GEMM
__device__ __align__(256) __nv_bfloat16 g_ahi[NN * 512];
__device__ __align__(256) __nv_bfloat16 g_alo[NN * 512];
__device__ __align__(256) __nv_bfloat16 g_bhi[512 * 512];
__device__ __align__(256) __nv_bfloat16 g_blo[512 * 512];

// ---------------- CSR build --------------------------------------------------
__global__ void zero_deg_kernel(int n) {
    int i = blockIdx.x * blockDim.x + threadIdx.x;
    if (i < n) g_deg[i] = 0;
}

__global__ void hist_dst_kernel(const int* __restrict__ dst, int E) {
    int i = blockIdx.x * blockDim.x + threadIdx.x;
    if (i < E) atomicAdd(&g_deg[dst[i]], 1);
}

__global__ void scan_exclusive_kernel(int n) {
    __shared__ int wsum[32];
    __shared__ int carry_s;
    int tid = threadIdx.x, lane = tid & 31, wid = tid >> 5;
    if (tid == 0) carry_s = 0;
    __syncthreads();
    for (int base = 0; base < n; base += blockDim.x) {
        int i = base + tid;
        int v = (i < n) ? g_deg[i] : 0;
        int x = v;
        #pragma unroll
        for (int o = 1; o < 32; o <<= 1) {
            int y = __shfl_up_sync(0xffffffffu, x, o);
            if (lane >= o) x += y;
        }
        if (lane == 31) wsum[wid] = x;
        __syncthreads();
        if (wid == 0) {
            int s = wsum[lane];
            #pragma unroll
            for (int o = 1; o < 32; o <<= 1) {
                int y = __shfl_up_sync(0xffffffffu, s, o);
                if (lane >= o) s += y;
            }
            wsum[lane] = s;
        }
        __syncthreads();
        int incl = x + (wid > 0 ? wsum[wid - 1] : 0) + carry_s;
        if (i < n) {
            g_rowptr[i] = incl - v;
            g_cursor[i] = incl - v;
        }
        __syncthreads();
        if (tid == blockDim.x - 1) carry_s = incl;
        __syncthreads();
    }
    if (tid == 0) g_rowptr[n] = carry_s;
}

__global__ void scatter_csr_kernel(const int* __restrict__ src,
                                   const int* __restrict__ dst, int E) {
    int i = blockIdx.x * blockDim.x + threadIdx.x;
    if (i < E) {
        int p = atomicAdd(&g_cursor[dst[i]], 1);
        g_csr_eid[p] = i;
        g_csr_src[p] = src[i];
    }
}

// ---------------- fp32 -> bf16 hi/lo split (4-wide) -------------------------
__global__ void split_bf16_kernel(const float4* __restrict__ in,
                                  __nv_bfloat162* __restrict__ hi,
                                  __nv_bfloat162* __restrict__ lo, int n4) {
    int i = blockIdx.x * blockDim.x + threadIdx.x;
    if (i >= n4) return;
    float4 x = in[i];
    __nv_bfloat16 hx = __float2bfloat16(x.x);
    __nv_bfloat16 hy = __float2bfloat16(x.y);
    __nv_bfloat16 hz = __float2bfloat16(x.z);
    __nv_bfloat16 hw = __float2bfloat16(x.w);
    hi[2 * i]     = __halves2bfloat162(hx, hy);
    hi[2 * i + 1] = __halves2bfloat162(hz, hw);
    lo[2 * i]     = __halves2bfloat162(__float2bfloat16(x.x - __bfloat162float(hx)),
                                       __float2bfloat16(x.y - __bfloat162float(hy)));
    lo[2 * i + 1] = __halves2bfloat162(__float2bfloat16(x.z - __bfloat162float(hz)),
                                       __float2bfloat16(x.w - __bfloat162float(hw)));
}

// ---------------- MMA helpers ------------------------------------------------
__device__ __forceinline__ void ldsm4(u32* r, const void* p) {
    u32 a = (u32)__cvta_generic_to_shared(p);
    asm volatile("ldmatrix.sync.aligned.m8n8.x4.shared.b16 {%0,%1,%2,%3}, [%4];"
                 : "=r"(r[0]), "=r"(r[1]), "=r"(r[2]), "=r"(r[3]) : "r"(a));
}
__device__ __forceinline__ void ldsm2t(u32* r, const void* p) {
    u32 a = (u32)__cvta_generic_to_shared(p);
    asm volatile("ldmatrix.sync.aligned.m8n8.x2.trans.shared.b16 {%0,%1}, [%2];"
                 : "=r"(r[0]), "=r"(r[1]) : "r"(a));
}
__device__ __forceinline__ void mma16816(float* d, const u32* a, const u32* b) {
    asm volatile("mma.sync.aligned.m16n8k16.row.col.f32.bf16.bf16.f32 "
                 "{%0,%1,%2,%3}, {%4,%5,%6,%7}, {%8,%9}, {%0,%1,%2,%3};"
                 : "+f"(d[0]), "+f"(d[1]), "+f"(d[2]), "+f"(d[3])
                 : "r"(a[0]), "r"(a[1]), "r"(a[2]), "r"(a[3]),
                   "r"(b[0]), "r"(b[1]));
}

// ---------------- bf16x3 tensor-core GEMM -----------------------------------
// C[MxN] fp32 = Ahi*Bhi + Ahi*Blo + Alo*Bhi  (bf16; row-major A[MxK], B[KxN])
// 128x128 block tile, BK=16, 256 threads = 8 warps (2x4), warp tile 64x32.
#define GBM 128
#define GBN 128
#define GBK 16
#define GSA 24
#define GSB 136

__global__ void __launch_bounds__(256)
gemm_bf16x3_kernel(const __nv_bfloat16* __restrict__ Ahi,
                   const __nv_bfloat16* __restrict__ Alo,
                   const __nv_bfloat16* __restrict__ Bhi,
                   const __nv_bfloat16* __restrict__ Blo,
                   float* __restrict__ C, int M, int N, int K) {
    __shared__ __nv_bfloat16 sAhi[GBM * GSA];
    __shared__ __nv_bfloat16 sAlo[GBM * GSA];
    __shared__ __nv_bfloat16 sBhi[GBK * GSB];
    __shared__ __nv_bfloat16 sBlo[GBK * GSB];

    int tid = threadIdx.x;
    int warp = tid >> 5;
    int lane = tid & 31;
    int wm = warp & 1;
    int wn = warp >> 1;
    int rowBase = blockIdx.y * GBM;
    int colBase = blockIdx.x * GBN;

    int aRow = tid >> 1;
    int aHalf = (tid & 1) * 8;
    int bRow = tid >> 4;
    int bCol = (tid & 15) * 8;

    float acc[4][4][4];
    #pragma unroll
    for (int i = 0; i < 4; i++) {
        #pragma unroll
        for (int j = 0; j < 4; j++) {
            #pragma unroll
            for (int k = 0; k < 4; k++) acc[i][j][k] = 0.f;
        }
    }

    int lrow = lane & 15;
    int lcol = (lane >> 4) * 8;

    for (int k0 = 0; k0 < K; k0 += GBK) {
        int gr = rowBase + aRow;
        uint4 vah = make_uint4(0u, 0u, 0u, 0u);
        uint4 valo = make_uint4(0u, 0u, 0u, 0u);
        if (gr < M) {
            vah  = *(const uint4*)(Ahi + (size_t)gr * K + k0 + aHalf);
            valo = *(const uint4*)(Alo + (size_t)gr * K + k0 + aHalf);
        }
        *(uint4*)(sAhi + aRow * GSA + aHalf) = vah;
        *(uint4*)(sAlo + aRow * GSA + aHalf) = valo;
        uint4 vbh = *(const uint4*)(Bhi + (size_t)(k0 + bRow) * N + colBase + bCol);
        uint4 vbl = *(const uint4*)(Blo + (size_t)(k0 + bRow) * N + colBase + bCol);
        *(uint4*)(sBhi + bRow * GSB + bCol) = vbh;
        *(uint4*)(sBlo + bRow * GSB + bCol) = vbl;
        __syncthreads();

        u32 fah[4][4];
        u32 fal[4][4];
        #pragma unroll
        for (int mt = 0; mt < 4; mt++) {
            ldsm4(fah[mt], sAhi + (wm * 64 + mt * 16 + lrow) * GSA + lcol);
            ldsm4(fal[mt], sAlo + (wm * 64 + mt * 16 + lrow) * GSA + lcol);
        }
        u32 fbh[4][2];
        u32 fbl[4][2];
        #pragma unroll
        for (int nt = 0; nt < 4; nt++) {
            ldsm2t(fbh[nt], sBhi + lrow * GSB + wn * 32 + nt * 8);
            ldsm2t(fbl[nt], sBlo + lrow * GSB + wn * 32 + nt * 8);
        }

        #pragma unroll
        for (int mt = 0; mt < 4; mt++) {
            #pragma unroll
            for (int nt = 0; nt < 4; nt++) {
                mma16816(acc[mt][nt], fah[mt], fbh[nt]);
                mma16816(acc[mt][nt], fah[mt], fbl[nt]);
                mma16816(acc[mt][nt], fal[mt], fbh[nt]);
            }
        }
        __syncthreads();
    }

    #pragma unroll
    for (int mt = 0; mt < 4; mt++) {
        #pragma unroll
        for (int nt = 0; nt < 4; nt++) {
            int r0 = rowBase + wm * 64 + mt * 16 + (lane >> 2);
            int c = colBase + wn * 32 + nt * 8 + (lane & 3) * 2;
            if (r0 < M) {
                *(float2*)(C + (size_t)r0 * N + c) =
                    make_float2(acc[mt][nt][0], acc[mt][nt][1]);
            }
            if (r0 + 8 < M) {
                *(float2*)(C + (size_t)(r0 + 8) * N + c) =
                    make_float2(acc[mt][nt][2], acc[mt][nt][3]);
            }
        }
    }
}

// ---------------- edge logits: warp per edge --------------------------------
__global__ void __launch_bounds__(256)
edge_logit_kernel(const float* __restrict__ fs, const float* __restrict__ fd,
                  const float* __restrict__ attn, const int* __restrict__ src,
                  const int* __restrict__ dst, int E, int D) {
    int gw = (blockIdx.x * blockDim.x + threadIdx.x) >> 5;
    int lane = threadIdx.x & 31;
    if (gw >= E) return;
    int HD = 4 * D;
    const float* ps = fs + (size_t)src[gw] * HD;
    const float* pd = fd + (size_t)dst[gw] * HD;
    float lg[4];
    #pragma unroll
    for (int h = 0; h < 4; h++) {
        float acc = 0.f;
        if (D == 128) {
            int o = h * 128 + lane * 4;
            float4 a = *(const float4*)(ps + o);
            float4 b = *(const float4*)(pd + o);
            float4 w = *(const float4*)(attn + o);
            float x;
            x = a.x + b.x; acc += w.x * (x > 0.f ? x : 0.2f * x);
            x = a.y + b.y; acc += w.y * (x > 0.f ? x : 0.2f * x);
            x = a.z + b.z; acc += w.z * (x > 0.f ? x : 0.2f * x);
            x = a.w + b.w; acc += w.w * (x > 0.f ? x : 0.2f * x);
        } else {
            int o = h * 64 + lane * 2;
            float2 a = *(const float2*)(ps + o);
            float2 b = *(const float2*)(pd + o);
            float2 w = *(const float2*)(attn + o);
            float x;
            x = a.x + b.x; acc += w.x * (x > 0.f ? x : 0.2f * x);
            x = a.y + b.y; acc += w.y * (x > 0.f ? x : 0.2f * x);
        }
        #pragma unroll
        for (int o = 16; o; o >>= 1) acc += __shfl_xor_sync(0xffffffffu, acc, o);
        lg[h] = acc;
    }
    if (lane == 0) {
        *(float4*)(g_logit + (size_t)gw * 4) = make_float4(lg[0], lg[1], lg[2], lg[3]);
    }
}

// ---------------- per-node softmax + aggregation + head-mean + leaky --------
__global__ void __launch_bounds__(128)
gat_agg_kernel(const float* __restrict__ fs, const float* __restrict__ b,
               float* __restrict__ hout, int D) {
    __shared__ float sh[512];
    int v = blockIdx.x;
    int lane = threadIdx.x & 31;
    int w = threadIdx.x >> 5;
    int HD = 4 * D;
    int e0 = g_rowptr[v], e1 = g_rowptr[v + 1];

    float mx = -INFINITY;
    for (int e = e0 + lane; e < e1; e += 32)
        mx = fmaxf(mx, g_logit[(size_t)g_csr_eid[e] * 4 + w]);
    #pragma unroll
    for (int o = 16; o; o >>= 1) mx = fmaxf(mx, __shfl_xor_sync(0xffffffffu, mx, o));

    float sm = 0.f;
    for (int e = e0 + lane; e < e1; e += 32)
        sm += __expf(g_logit[(size_t)g_csr_eid[e] * 4 + w] - mx);
    #pragma unroll
    for (int o = 16; o; o >>= 1) sm += __shfl_xor_sync(0xffffffffu, sm, o);
    float inv = (e1 > e0) ? 1.f / sm : 0.f;

    float a0 = 0.f, a1 = 0.f, a2 = 0.f, a3 = 0.f;
    if (D == 128) {
        const int off = w * 128 + lane * 4;
        for (int e = e0; e < e1; e++) {
            float alpha = __expf(g_logit[(size_t)g_csr_eid[e] * 4 + w] - mx) * inv;
            float4 t = *(const float4*)(fs + (size_t)g_csr_src[e] * HD + off);
            a0 += alpha * t.x; a1 += alpha * t.y; a2 += alpha * t.z; a3 += alpha * t.w;
        }
        sh[off] = a0; sh[off + 1] = a1; sh[off + 2] = a2; sh[off + 3] = a3;
    } else {
        const int off = w * 64 + lane * 2;
        for (int e = e0; e < e1; e++) {
            float alpha = __expf(g_logit[(size_t)g_csr_eid[e] * 4 + w] - mx) * inv;
            float2 t = *(const float2*)(fs + (size_t)g_csr_src[e] * HD + off);
            a0 += alpha * t.x; a1 += alpha * t.y;
        }
        sh[off] = a0; sh[off + 1] = a1;
    }
    __syncthreads();

    if (threadIdx.x < D) {
        int t = threadIdx.x;
        float m = 0.f;
        #pragma unroll
        for (int h = 0; h < 4; h++) m += sh[h * D + t] + b[h * D + t];
        m *= 0.25f;
        hout[(size_t)v * D + t] = (m > 0.f) ? m : 0.01f * m;
    }
}

// ---------------- final node-mean readout -----------------------------------
__global__ void node_mean_kernel(const float* __restrict__ hin,
                                 float* __restrict__ out, int n, int D) {
    int d = blockIdx.x;
    float s = 0.f;
    for (int v = threadIdx.x; v < n; v += blockDim.x)
        s += hin[(size_t)v * D + d];
    __shared__ float red[256];
    red[threadIdx.x] = s;
    __syncthreads();
    for (int o = 128; o; o >>= 1) {
        if (threadIdx.x < o) red[threadIdx.x] += red[threadIdx.x + o];
        __syncthreads();
    }
    if (threadIdx.x == 0) out[d] = red[0] / (float)n;
}

// ---------------- launch ----------------------------------------------------
extern "C" void kernel_launch(void* const* d_in, const int* in_sizes, int n_in,
                              void* d_out, int out_size) {
    const float* n_feat = (const float*)d_in[0];
    const int*   src    = (const int*)d_in[1];
    const int*   dst    = (const int*)d_in[2];
    const float* Wl0 = (const float*)d_in[3];
    const float* Wr0 = (const float*)d_in[4];
    const float* attn0 = (const float*)d_in[5];
    const float* b0 = (const float*)d_in[6];
    const float* Wl1 = (const float*)d_in[7];
    const float* Wr1 = (const float*)d_in[8];
    const float* attn1 = (const float*)d_in[9];
    const float* b1 = (const float*)d_in[10];
    const float* Wl2 = (const float*)d_in[11];
    const float* Wr2 = (const float*)d_in[12];
    const float* attn2 = (const float*)d_in[13];
    const float* b2 = (const float*)d_in[14];
    float* out = (float*)d_out;

    int n = in_sizes[0] / 512;   // 20000
    int E = in_sizes[1];         // 320000

    float* fs;
    float* fd;
    float* hin;
    __nv_bfloat16* ahi;
    __nv_bfloat16* alo;
    __nv_bfloat16* bhi;
    __nv_bfloat16* blo;
    cudaGetSymbolAddress((void**)&fs, g_fs);
    cudaGetSymbolAddress((void**)&fd, g_fd);
    cudaGetSymbolAddress((void**)&hin, g_hin);
    cudaGetSymbolAddress((void**)&ahi, g_ahi);
    cudaGetSymbolAddress((void**)&alo, g_alo);
    cudaGetSymbolAddress((void**)&bhi, g_bhi);
    cudaGetSymbolAddress((void**)&blo, g_blo);

    // CSR by dst
    zero_deg_kernel<<<(n + 255) / 256, 256>>>(n);
    hist_dst_kernel<<<(E + 255) / 256, 256>>>(dst, E);
    scan_exclusive_kernel<<<1, 1024>>>(n);
    scatter_csr_kernel<<<(E + 255) / 256, 256>>>(src, dst, E);

    int eblocks = (E + 7) / 8;
    int mtiles = (n + 127) / 128;

    // ---- layer 0: 512 -> 4x128
    split_bf16_kernel<<<(n * 512 / 4 + 255) / 256, 256>>>(
        (const float4*)n_feat, (__nv_bfloat162*)ahi, (__nv_bfloat162*)alo, n * 512 / 4);
    split_bf16_kernel<<<(512 * 512 / 4 + 255) / 256, 256>>>(
        (const float4*)Wl0, (__nv_bfloat162*)bhi, (__nv_bfloat162*)blo, 512 * 512 / 4);
    gemm_bf16x3_kernel<<<dim3(4, mtiles), 256>>>(ahi, alo, bhi, blo, fs, n, 512, 512);
    split_bf16_kernel<<<(512 * 512 / 4 + 255) / 256, 256>>>(
        (const float4*)Wr0, (__nv_bfloat162*)bhi, (__nv_bfloat162*)blo, 512 * 512 / 4);
    gemm_bf16x3_kernel<<<dim3(4, mtiles), 256>>>(ahi, alo, bhi, blo, fd, n, 512, 512);
    edge_logit_kernel<<<eblocks, 256>>>(fs, fd, attn0, src, dst, E, 128);
    gat_agg_kernel<<<n, 128>>>(fs, b0, hin, 128);

    // ---- layer 1: 128 -> 4x128
    split_bf16_kernel<<<(n * 128 / 4 + 255) / 256, 256>>>(
        (const float4*)hin, (__nv_bfloat162*)ahi, (__nv_bfloat162*)alo, n * 128 / 4);
    split_bf16_kernel<<<(128 * 512 / 4 + 255) / 256, 256>>>(
        (const float4*)Wl1, (__nv_bfloat162*)bhi, (__nv_bfloat162*)blo, 128 * 512 / 4);
    gemm_bf16x3_kernel<<<dim3(4, mtiles), 256>>>(ahi, alo, bhi, blo, fs, n, 512, 128);
    split_bf16_kernel<<<(128 * 512 / 4 + 255) / 256, 256>>>(
        (const float4*)Wr1, (__nv_bfloat162*)bhi, (__nv_bfloat162*)blo, 128 * 512 / 4);
    gemm_bf16x3_kernel<<<dim3(4, mtiles), 256>>>(ahi, alo, bhi, blo, fd, n, 512, 128);
    edge_logit_kernel<<<eblocks, 256>>>(fs, fd, attn1, src, dst, E, 128);
    gat_agg_kernel<<<n, 128>>>(fs, b1, hin, 128);

    // ---- layer 2: 128 -> 4x64
    split_bf16_kernel<<<(n * 128 / 4 + 255) / 256, 256>>>(
        (const float4*)hin, (__nv_bfloat162*)ahi, (__nv_bfloat162*)alo, n * 128 / 4);
    split_bf16_kernel<<<(128 * 256 / 4 + 255) / 256, 256>>>(
        (const float4*)Wl2, (__nv_bfloat162*)bhi, (__nv_bfloat162*)blo, 128 * 256 / 4);
    gemm_bf16x3_kernel<<<dim3(2, mtiles), 256>>>(ahi, alo, bhi, blo, fs, n, 256, 128);
    split_bf16_kernel<<<(128 * 256 / 4 + 255) / 256, 256>>>(
        (const float4*)Wr2, (__nv_bfloat162*)bhi, (__nv_bfloat162*)blo, 128 * 256 / 4);
    gemm_bf16x3_kernel<<<dim3(2, mtiles), 256>>>(ahi, alo, bhi, blo, fd, n, 256, 128);
    edge_logit_kernel<<<eblocks, 256>>>(fs, fd, attn2, src, dst, E, 64);
    gat_agg_kernel<<<n, 128>>>(fs, b2, hin, 64);

    node_mean_kernel<<<64, 256>>>(hin, out, n, 64);
}

// round 7
// speedup vs baseline: 2.1701x; 1.4778x over previous
#include <cuda_runtime.h>
#include <cuda_bf16.h>
#include <stdint.h>
#include <stddef.h>
#include <math.h>

typedef unsigned int u32;

#define NN 20000
#define EE 320000

// ---------------- scratch (device globals; no allocations allowed) ----------
__device__ __align__(256) float g_fsd[NN * 1024];   // [fs | fd] merged, row stride 8*D
__device__ __align__(256) float g_hin[NN * 128];
__device__ __align__(256) int   g_deg[NN];
__device__ __align__(256) int   g_rowptr[NN + 1];
__device__ __align__(256) int   g_cursor[NN];
__device__ __align__(256) int   g_csr_src[EE];
// bf16 hi/lo split buffers for tensor-core GEMM
__device__ __align__(256) __nv_bfloat16 g_ahi[NN * 512];
__device__ __align__(256) __nv_bfloat16 g_alo[NN * 512];
__device__ __align__(256) __nv_bfloat16 g_bhi[512 * 1024];
__device__ __align__(256) __nv_bfloat16 g_blo[512 * 1024];

// ---------------- CSR build --------------------------------------------------
__global__ void zero_deg_kernel(int n) {
    int i = blockIdx.x * blockDim.x + threadIdx.x;
    if (i < n) g_deg[i] = 0;
}

__global__ void hist_dst_kernel(const int* __restrict__ dst, int E) {
    int i = blockIdx.x * blockDim.x + threadIdx.x;
    if (i < E) atomicAdd(&g_deg[dst[i]], 1);
}

__global__ void scan_exclusive_kernel(int n) {
    __shared__ int wsum[32];
    __shared__ int carry_s;
    int tid = threadIdx.x, lane = tid & 31, wid = tid >> 5;
    if (tid == 0) carry_s = 0;
    __syncthreads();
    for (int base = 0; base < n; base += blockDim.x) {
        int i = base + tid;
        int v = (i < n) ? g_deg[i] : 0;
        int x = v;
        #pragma unroll
        for (int o = 1; o < 32; o <<= 1) {
            int y = __shfl_up_sync(0xffffffffu, x, o);
            if (lane >= o) x += y;
        }
        if (lane == 31) wsum[wid] = x;
        __syncthreads();
        if (wid == 0) {
            int s = wsum[lane];
            #pragma unroll
            for (int o = 1; o < 32; o <<= 1) {
                int y = __shfl_up_sync(0xffffffffu, s, o);
                if (lane >= o) s += y;
            }
            wsum[lane] = s;
        }
        __syncthreads();
        int incl = x + (wid > 0 ? wsum[wid - 1] : 0) + carry_s;
        if (i < n) {
            g_rowptr[i] = incl - v;
            g_cursor[i] = incl - v;
        }
        __syncthreads();
        if (tid == blockDim.x - 1) carry_s = incl;
        __syncthreads();
    }
    if (tid == 0) g_rowptr[n] = carry_s;
}

__global__ void scatter_csr_kernel(const int* __restrict__ src,
                                   const int* __restrict__ dst, int E) {
    int i = blockIdx.x * blockDim.x + threadIdx.x;
    if (i < E) {
        int p = atomicAdd(&g_cursor[dst[i]], 1);
        g_csr_src[p] = src[i];
    }
}

// ---------------- fp32 -> bf16 hi/lo splits ---------------------------------
__global__ void split_bf16_kernel(const float4* __restrict__ in,
                                  __nv_bfloat162* __restrict__ hi,
                                  __nv_bfloat162* __restrict__ lo, int n4) {
    int i = blockIdx.x * blockDim.x + threadIdx.x;
    if (i >= n4) return;
    float4 x = in[i];
    __nv_bfloat16 hx = __float2bfloat16(x.x);
    __nv_bfloat16 hy = __float2bfloat16(x.y);
    __nv_bfloat16 hz = __float2bfloat16(x.z);
    __nv_bfloat16 hw = __float2bfloat16(x.w);
    hi[2 * i]     = __halves2bfloat162(hx, hy);
    hi[2 * i + 1] = __halves2bfloat162(hz, hw);
    lo[2 * i]     = __halves2bfloat162(__float2bfloat16(x.x - __bfloat162float(hx)),
                                       __float2bfloat16(x.y - __bfloat162float(hy)));
    lo[2 * i + 1] = __halves2bfloat162(__float2bfloat16(x.z - __bfloat162float(hz)),
                                       __float2bfloat16(x.w - __bfloat162float(hw)));
}

// split weight W[K][Nw] into merged buffer [K][Ntot] at column offset colOff
__global__ void split_w_kernel(const float4* __restrict__ in,
                               __nv_bfloat162* __restrict__ hi,
                               __nv_bfloat162* __restrict__ lo,
                               int n4, int Nw, int Ntot, int colOff) {
    int i = blockIdx.x * blockDim.x + threadIdx.x;
    if (i >= n4) return;
    float4 x = in[i];
    int j = i * 4;
    int k = j / Nw;
    int nn = j - k * Nw;
    int o2 = (k * Ntot + colOff + nn) >> 1;
    __nv_bfloat16 hx = __float2bfloat16(x.x);
    __nv_bfloat16 hy = __float2bfloat16(x.y);
    __nv_bfloat16 hz = __float2bfloat16(x.z);
    __nv_bfloat16 hw = __float2bfloat16(x.w);
    hi[o2]     = __halves2bfloat162(hx, hy);
    hi[o2 + 1] = __halves2bfloat162(hz, hw);
    lo[o2]     = __halves2bfloat162(__float2bfloat16(x.x - __bfloat162float(hx)),
                                    __float2bfloat16(x.y - __bfloat162float(hy)));
    lo[o2 + 1] = __halves2bfloat162(__float2bfloat16(x.z - __bfloat162float(hz)),
                                    __float2bfloat16(x.w - __bfloat162float(hw)));
}

// ---------------- MMA / cp.async helpers ------------------------------------
__device__ __forceinline__ void ldsm4(u32* r, const void* p) {
    u32 a = (u32)__cvta_generic_to_shared(p);
    asm volatile("ldmatrix.sync.aligned.m8n8.x4.shared.b16 {%0,%1,%2,%3}, [%4];"
                 : "=r"(r[0]), "=r"(r[1]), "=r"(r[2]), "=r"(r[3]) : "r"(a));
}
__device__ __forceinline__ void ldsm2t(u32* r, const void* p) {
    u32 a = (u32)__cvta_generic_to_shared(p);
    asm volatile("ldmatrix.sync.aligned.m8n8.x2.trans.shared.b16 {%0,%1}, [%2];"
                 : "=r"(r[0]), "=r"(r[1]) : "r"(a));
}
__device__ __forceinline__ void mma16816(float* d, const u32* a, const u32* b) {
    asm volatile("mma.sync.aligned.m16n8k16.row.col.f32.bf16.bf16.f32 "
                 "{%0,%1,%2,%3}, {%4,%5,%6,%7}, {%8,%9}, {%0,%1,%2,%3};"
                 : "+f"(d[0]), "+f"(d[1]), "+f"(d[2]), "+f"(d[3])
                 : "r"(a[0]), "r"(a[1]), "r"(a[2]), "r"(a[3]),
                   "r"(b[0]), "r"(b[1]));
}
__device__ __forceinline__ void cpa16(void* smem, const void* g, int sz) {
    u32 a = (u32)__cvta_generic_to_shared(smem);
    asm volatile("cp.async.cg.shared.global [%0], [%1], 16, %2;"
                 :: "r"(a), "l"(g), "r"(sz));
}
#define CP_COMMIT asm volatile("cp.async.commit_group;")
#define CP_WAIT1  asm volatile("cp.async.wait_group 1;")
#define CP_WAIT0  asm volatile("cp.async.wait_group 0;")

// ---------------- bf16x3 tensor-core GEMM (2-stage cp.async pipeline) -------
#define GBM 128
#define GBN 128
#define GBK 16
#define GSA 24
#define GSB 136

__global__ void __launch_bounds__(256)
gemm_bf16x3_kernel(const __nv_bfloat16* __restrict__ Ahi,
                   const __nv_bfloat16* __restrict__ Alo,
                   const __nv_bfloat16* __restrict__ Bhi,
                   const __nv_bfloat16* __restrict__ Blo,
                   float* __restrict__ C, int M, int N, int K) {
    __shared__ __nv_bfloat16 sAhi[2][GBM * GSA];
    __shared__ __nv_bfloat16 sAlo[2][GBM * GSA];
    __shared__ __nv_bfloat16 sBhi[2][GBK * GSB];
    __shared__ __nv_bfloat16 sBlo[2][GBK * GSB];

    int tid = threadIdx.x;
    int warp = tid >> 5;
    int lane = tid & 31;
    int wm = warp & 1;
    int wn = warp >> 1;
    int rowBase = blockIdx.y * GBM;
    int colBase = blockIdx.x * GBN;

    int aRow = tid >> 1;
    int aHalf = (tid & 1) * 8;
    int bRow = tid >> 4;
    int bCol = (tid & 15) * 8;

    int gr = rowBase + aRow;
    int aSz = (gr < M) ? 16 : 0;
    size_t aOff = (size_t)(gr < M ? gr : 0) * K + aHalf;
    size_t bOffBase = (size_t)bRow * N + colBase + bCol;

    float acc[4][4][4];
    #pragma unroll
    for (int i = 0; i < 4; i++) {
        #pragma unroll
        for (int j = 0; j < 4; j++) {
            #pragma unroll
            for (int k = 0; k < 4; k++) acc[i][j][k] = 0.f;
        }
    }

    int lrow = lane & 15;
    int lcol = (lane >> 4) * 8;
    int KT = K / GBK;

    // prologue: stage 0
    cpa16(&sAhi[0][aRow * GSA + aHalf], Ahi + aOff, aSz);
    cpa16(&sAlo[0][aRow * GSA + aHalf], Alo + aOff, aSz);
    cpa16(&sBhi[0][bRow * GSB + bCol], Bhi + bOffBase, 16);
    cpa16(&sBlo[0][bRow * GSB + bCol], Blo + bOffBase, 16);
    CP_COMMIT;

    for (int kt = 0; kt < KT; kt++) {
        int st = kt & 1;
        if (kt + 1 < KT) {
            int ns = st ^ 1;
            int kk = (kt + 1) * GBK;
            cpa16(&sAhi[ns][aRow * GSA + aHalf], Ahi + aOff + kk, aSz);
            cpa16(&sAlo[ns][aRow * GSA + aHalf], Alo + aOff + kk, aSz);
            cpa16(&sBhi[ns][bRow * GSB + bCol], Bhi + bOffBase + (size_t)kk * N, 16);
            cpa16(&sBlo[ns][bRow * GSB + bCol], Blo + bOffBase + (size_t)kk * N, 16);
            CP_COMMIT;
            CP_WAIT1;
        } else {
            CP_WAIT0;
        }
        __syncthreads();

        u32 fah[4][4];
        u32 fal[4][4];
        #pragma unroll
        for (int mt = 0; mt < 4; mt++) {
            ldsm4(fah[mt], &sAhi[st][(wm * 64 + mt * 16 + lrow) * GSA + lcol]);
            ldsm4(fal[mt], &sAlo[st][(wm * 64 + mt * 16 + lrow) * GSA + lcol]);
        }
        u32 fbh[4][2];
        u32 fbl[4][2];
        #pragma unroll
        for (int nt = 0; nt < 4; nt++) {
            ldsm2t(fbh[nt], &sBhi[st][lrow * GSB + wn * 32 + nt * 8]);
            ldsm2t(fbl[nt], &sBlo[st][lrow * GSB + wn * 32 + nt * 8]);
        }

        #pragma unroll
        for (int mt = 0; mt < 4; mt++) {
            #pragma unroll
            for (int nt = 0; nt < 4; nt++) {
                mma16816(acc[mt][nt], fah[mt], fbh[nt]);
                mma16816(acc[mt][nt], fah[mt], fbl[nt]);
                mma16816(acc[mt][nt], fal[mt], fbh[nt]);
            }
        }
        __syncthreads();
    }

    #pragma unroll
    for (int mt = 0; mt < 4; mt++) {
        #pragma unroll
        for (int nt = 0; nt < 4; nt++) {
            int r0 = rowBase + wm * 64 + mt * 16 + (lane >> 2);
            int c = colBase + wn * 32 + nt * 8 + (lane & 3) * 2;
            if (r0 < M) {
                *(float2*)(C + (size_t)r0 * N + c) =
                    make_float2(acc[mt][nt][0], acc[mt][nt][1]);
            }
            if (r0 + 8 < M) {
                *(float2*)(C + (size_t)(r0 + 8) * N + c) =
                    make_float2(acc[mt][nt][2], acc[mt][nt][3]);
            }
        }
    }
}

// ---------------- fused online-softmax GAT aggregation ----------------------
// block = 128 threads, warp w = head w; one block per dst node v.
// fsd row layout: [fs(0..4D-1) | fd(0..4D-1)], row stride 8*D.
__global__ void __launch_bounds__(128)
gat_fused_kernel(const float* __restrict__ fsd, const float* __restrict__ attn,
                 const float* __restrict__ b, float* __restrict__ hout, int D) {
    __shared__ float sh[512];
    int v = blockIdx.x;
    int lane = threadIdx.x & 31;
    int w = threadIdx.x >> 5;
    int Ntot = 8 * D;
    int half = 4 * D;
    int e0 = g_rowptr[v], e1 = g_rowptr[v + 1];

    if (D == 128) {
        int off = w * 128 + lane * 4;
        float4 fdv = *(const float4*)(fsd + (size_t)v * Ntot + half + off);
        float4 aw = *(const float4*)(attn + off);
        float m = -INFINITY, ssum = 0.f;
        float a0 = 0.f, a1 = 0.f, a2 = 0.f, a3 = 0.f;
        for (int e = e0; e < e1; e++) {
            int s = g_csr_src[e];
            float4 fv = *(const float4*)(fsd + (size_t)s * Ntot + off);
            float x, p = 0.f;
            x = fv.x + fdv.x; p += aw.x * (x > 0.f ? x : 0.2f * x);
            x = fv.y + fdv.y; p += aw.y * (x > 0.f ? x : 0.2f * x);
            x = fv.z + fdv.z; p += aw.z * (x > 0.f ? x : 0.2f * x);
            x = fv.w + fdv.w; p += aw.w * (x > 0.f ? x : 0.2f * x);
            #pragma unroll
            for (int o = 16; o; o >>= 1) p += __shfl_xor_sync(0xffffffffu, p, o);
            float logit = p;
            if (logit <= m) {
                float q = __expf(logit - m);
                ssum += q;
                a0 += q * fv.x; a1 += q * fv.y; a2 += q * fv.z; a3 += q * fv.w;
            } else {
                float c = __expf(m - logit);   // exp(-inf)=0 on first edge
                ssum = ssum * c + 1.f;
                a0 = a0 * c + fv.x; a1 = a1 * c + fv.y;
                a2 = a2 * c + fv.z; a3 = a3 * c + fv.w;
                m = logit;
            }
        }
        float inv = (e1 > e0) ? 1.f / ssum : 0.f;
        sh[off] = a0 * inv; sh[off + 1] = a1 * inv;
        sh[off + 2] = a2 * inv; sh[off + 3] = a3 * inv;
    } else { // D == 64
        int off = w * 64 + lane * 2;
        float2 fdv = *(const float2*)(fsd + (size_t)v * Ntot + half + off);
        float2 aw = *(const float2*)(attn + off);
        float m = -INFINITY, ssum = 0.f;
        float a0 = 0.f, a1 = 0.f;
        for (int e = e0; e < e1; e++) {
            int s = g_csr_src[e];
            float2 fv = *(const float2*)(fsd + (size_t)s * Ntot + off);
            float x, p = 0.f;
            x = fv.x + fdv.x; p += aw.x * (x > 0.f ? x : 0.2f * x);
            x = fv.y + fdv.y; p += aw.y * (x > 0.f ? x : 0.2f * x);
            #pragma unroll
            for (int o = 16; o; o >>= 1) p += __shfl_xor_sync(0xffffffffu, p, o);
            float logit = p;
            if (logit <= m) {
                float q = __expf(logit - m);
                ssum += q;
                a0 += q * fv.x; a1 += q * fv.y;
            } else {
                float c = __expf(m - logit);
                ssum = ssum * c + 1.f;
                a0 = a0 * c + fv.x; a1 = a1 * c + fv.y;
                m = logit;
            }
        }
        float inv = (e1 > e0) ? 1.f / ssum : 0.f;
        sh[off] = a0 * inv; sh[off + 1] = a1 * inv;
    }
    __syncthreads();

    if (threadIdx.x < D) {
        int t = threadIdx.x;
        float m = 0.f;
        #pragma unroll
        for (int h = 0; h < 4; h++) m += sh[h * D + t] + b[h * D + t];
        m *= 0.25f;
        hout[(size_t)v * D + t] = (m > 0.f) ? m : 0.01f * m;
    }
}

// ---------------- final node-mean readout -----------------------------------
__global__ void node_mean_kernel(const float* __restrict__ hin,
                                 float* __restrict__ out, int n, int D) {
    int d = blockIdx.x;
    float s = 0.f;
    for (int v = threadIdx.x; v < n; v += blockDim.x)
        s += hin[(size_t)v * D + d];
    __shared__ float red[256];
    red[threadIdx.x] = s;
    __syncthreads();
    for (int o = 128; o; o >>= 1) {
        if (threadIdx.x < o) red[threadIdx.x] += red[threadIdx.x + o];
        __syncthreads();
    }
    if (threadIdx.x == 0) out[d] = red[0] / (float)n;
}

// ---------------- launch ----------------------------------------------------
extern "C" void kernel_launch(void* const* d_in, const int* in_sizes, int n_in,
                              void* d_out, int out_size) {
    const float* n_feat = (const float*)d_in[0];
    const int*   src    = (const int*)d_in[1];
    const int*   dst    = (const int*)d_in[2];
    const float* Wl0 = (const float*)d_in[3];
    const float* Wr0 = (const float*)d_in[4];
    const float* attn0 = (const float*)d_in[5];
    const float* b0 = (const float*)d_in[6];
    const float* Wl1 = (const float*)d_in[7];
    const float* Wr1 = (const float*)d_in[8];
    const float* attn1 = (const float*)d_in[9];
    const float* b1 = (const float*)d_in[10];
    const float* Wl2 = (const float*)d_in[11];
    const float* Wr2 = (const float*)d_in[12];
    const float* attn2 = (const float*)d_in[13];
    const float* b2 = (const float*)d_in[14];
    float* out = (float*)d_out;

    int n = in_sizes[0] / 512;   // 20000
    int E = in_sizes[1];         // 320000

    float* fsd;
    float* hin;
    __nv_bfloat16* ahi;
    __nv_bfloat16* alo;
    __nv_bfloat16* bhi;
    __nv_bfloat16* blo;
    cudaGetSymbolAddress((void**)&fsd, g_fsd);
    cudaGetSymbolAddress((void**)&hin, g_hin);
    cudaGetSymbolAddress((void**)&ahi, g_ahi);
    cudaGetSymbolAddress((void**)&alo, g_alo);
    cudaGetSymbolAddress((void**)&bhi, g_bhi);
    cudaGetSymbolAddress((void**)&blo, g_blo);

    // CSR by dst
    zero_deg_kernel<<<(n + 255) / 256, 256>>>(n);
    hist_dst_kernel<<<(E + 255) / 256, 256>>>(dst, E);
    scan_exclusive_kernel<<<1, 1024>>>(n);
    scatter_csr_kernel<<<(E + 255) / 256, 256>>>(src, dst, E);

    int mtiles = (n + 127) / 128;

    // ---- layer 0: 512 -> 4x128 (merged Wl|Wr GEMM, N=1024)
    split_bf16_kernel<<<(n * 512 / 4 + 255) / 256, 256>>>(
        (const float4*)n_feat, (__nv_bfloat162*)ahi, (__nv_bfloat162*)alo, n * 512 / 4);
    split_w_kernel<<<(512 * 512 / 4 + 255) / 256, 256>>>(
        (const float4*)Wl0, (__nv_bfloat162*)bhi, (__nv_bfloat162*)blo,
        512 * 512 / 4, 512, 1024, 0);
    split_w_kernel<<<(512 * 512 / 4 + 255) / 256, 256>>>(
        (const float4*)Wr0, (__nv_bfloat162*)bhi, (__nv_bfloat162*)blo,
        512 * 512 / 4, 512, 1024, 512);
    gemm_bf16x3_kernel<<<dim3(8, mtiles), 256>>>(ahi, alo, bhi, blo, fsd, n, 1024, 512);
    gat_fused_kernel<<<n, 128>>>(fsd, attn0, b0, hin, 128);

    // ---- layer 1: 128 -> 4x128
    split_bf16_kernel<<<(n * 128 / 4 + 255) / 256, 256>>>(
        (const float4*)hin, (__nv_bfloat162*)ahi, (__nv_bfloat162*)alo, n * 128 / 4);
    split_w_kernel<<<(128 * 512 / 4 + 255) / 256, 256>>>(
        (const float4*)Wl1, (__nv_bfloat162*)bhi, (__nv_bfloat162*)blo,
        128 * 512 / 4, 512, 1024, 0);
    split_w_kernel<<<(128 * 512 / 4 + 255) / 256, 256>>>(
        (const float4*)Wr1, (__nv_bfloat162*)bhi, (__nv_bfloat162*)blo,
        128 * 512 / 4, 512, 1024, 512);
    gemm_bf16x3_kernel<<<dim3(8, mtiles), 256>>>(ahi, alo, bhi, blo, fsd, n, 1024, 128);
    gat_fused_kernel<<<n, 128>>>(fsd, attn1, b1, hin, 128);

    // ---- layer 2: 128 -> 4x64
    split_bf16_kernel<<<(n * 128 / 4 + 255) / 256, 256>>>(
        (const float4*)hin, (__nv_bfloat162*)ahi, (__nv_bfloat162*)alo, n * 128 / 4);
    split_w_kernel<<<(128 * 256 / 4 + 255) / 256, 256>>>(
        (const float4*)Wl2, (__nv_bfloat162*)bhi, (__nv_bfloat162*)blo,
        128 * 256 / 4, 256, 512, 0);
    split_w_kernel<<<(128 * 256 / 4 + 255) / 256, 256>>>(
        (const float4*)Wr2, (__nv_bfloat162*)bhi, (__nv_bfloat162*)blo,
        128 * 256 / 4, 256, 512, 256);
    gemm_bf16x3_kernel<<<dim3(4, mtiles), 256>>>(ahi, alo, bhi, blo, fsd, n, 512, 128);
    gat_fused_kernel<<<n, 128>>>(fsd, attn2, b2, hin, 64);

    node_mean_kernel<<<64, 256>>>(hin, out, n, 64);
}

// round 8
// speedup vs baseline: 2.2938x; 1.0570x over previous
#include <cuda_runtime.h>
#include <cuda_bf16.h>
#include <stdint.h>
#include <stddef.h>
#include <math.h>

typedef unsigned int u32;

#define NN 20000
#define EE 320000

// ---------------- scratch (device globals; no allocations allowed) ----------
__device__ __align__(256) float g_fsd[NN * 1024];   // [fs | fd] merged, row stride 8*D
__device__ __align__(256) float g_hin[NN * 128];
__device__ __align__(256) int   g_deg[NN];
__device__ __align__(256) int   g_rowptr[NN + 1];
__device__ __align__(256) int   g_cursor[NN];
__device__ __align__(256) int   g_csr_src[EE];
// bf16 hi/lo split buffers for tensor-core GEMM
__device__ __align__(256) __nv_bfloat16 g_ahi[NN * 512];
__device__ __align__(256) __nv_bfloat16 g_alo[NN * 512];
__device__ __align__(256) __nv_bfloat16 g_bhi[512 * 1024];
__device__ __align__(256) __nv_bfloat16 g_blo[512 * 1024];

// ---------------- CSR build --------------------------------------------------
__global__ void zero_deg_kernel(int n) {
    int i = blockIdx.x * blockDim.x + threadIdx.x;
    if (i < n) g_deg[i] = 0;
}

__global__ void hist_dst_kernel(const int* __restrict__ dst, int E) {
    int i = blockIdx.x * blockDim.x + threadIdx.x;
    if (i < E) atomicAdd(&g_deg[dst[i]], 1);
}

__global__ void scan_exclusive_kernel(int n) {
    __shared__ int wsum[32];
    __shared__ int carry_s;
    int tid = threadIdx.x, lane = tid & 31, wid = tid >> 5;
    if (tid == 0) carry_s = 0;
    __syncthreads();
    for (int base = 0; base < n; base += blockDim.x) {
        int i = base + tid;
        int v = (i < n) ? g_deg[i] : 0;
        int x = v;
        #pragma unroll
        for (int o = 1; o < 32; o <<= 1) {
            int y = __shfl_up_sync(0xffffffffu, x, o);
            if (lane >= o) x += y;
        }
        if (lane == 31) wsum[wid] = x;
        __syncthreads();
        if (wid == 0) {
            int s = wsum[lane];
            #pragma unroll
            for (int o = 1; o < 32; o <<= 1) {
                int y = __shfl_up_sync(0xffffffffu, s, o);
                if (lane >= o) s += y;
            }
            wsum[lane] = s;
        }
        __syncthreads();
        int incl = x + (wid > 0 ? wsum[wid - 1] : 0) + carry_s;
        if (i < n) {
            g_rowptr[i] = incl - v;
            g_cursor[i] = incl - v;
        }
        __syncthreads();
        if (tid == blockDim.x - 1) carry_s = incl;
        __syncthreads();
    }
    if (tid == 0) g_rowptr[n] = carry_s;
}

__global__ void scatter_csr_kernel(const int* __restrict__ src,
                                   const int* __restrict__ dst, int E) {
    int i = blockIdx.x * blockDim.x + threadIdx.x;
    if (i < E) {
        int p = atomicAdd(&g_cursor[dst[i]], 1);
        g_csr_src[p] = src[i];
    }
}

// ---------------- fp32 -> bf16 hi/lo splits ---------------------------------
__global__ void split_bf16_kernel(const float4* __restrict__ in,
                                  __nv_bfloat162* __restrict__ hi,
                                  __nv_bfloat162* __restrict__ lo, int n4) {
    int i = blockIdx.x * blockDim.x + threadIdx.x;
    if (i >= n4) return;
    float4 x = in[i];
    __nv_bfloat16 hx = __float2bfloat16(x.x);
    __nv_bfloat16 hy = __float2bfloat16(x.y);
    __nv_bfloat16 hz = __float2bfloat16(x.z);
    __nv_bfloat16 hw = __float2bfloat16(x.w);
    hi[2 * i]     = __halves2bfloat162(hx, hy);
    hi[2 * i + 1] = __halves2bfloat162(hz, hw);
    lo[2 * i]     = __halves2bfloat162(__float2bfloat16(x.x - __bfloat162float(hx)),
                                       __float2bfloat16(x.y - __bfloat162float(hy)));
    lo[2 * i + 1] = __halves2bfloat162(__float2bfloat16(x.z - __bfloat162float(hz)),
                                       __float2bfloat16(x.w - __bfloat162float(hw)));
}

// split weight W[K][Nw] into merged buffer [K][Ntot] at column offset colOff
__global__ void split_w_kernel(const float4* __restrict__ in,
                               __nv_bfloat162* __restrict__ hi,
                               __nv_bfloat162* __restrict__ lo,
                               int n4, int Nw, int Ntot, int colOff) {
    int i = blockIdx.x * blockDim.x + threadIdx.x;
    if (i >= n4) return;
    float4 x = in[i];
    int j = i * 4;
    int k = j / Nw;
    int nn = j - k * Nw;
    int o2 = (k * Ntot + colOff + nn) >> 1;
    __nv_bfloat16 hx = __float2bfloat16(x.x);
    __nv_bfloat16 hy = __float2bfloat16(x.y);
    __nv_bfloat16 hz = __float2bfloat16(x.z);
    __nv_bfloat16 hw = __float2bfloat16(x.w);
    hi[o2]     = __halves2bfloat162(hx, hy);
    hi[o2 + 1] = __halves2bfloat162(hz, hw);
    lo[o2]     = __halves2bfloat162(__float2bfloat16(x.x - __bfloat162float(hx)),
                                    __float2bfloat16(x.y - __bfloat162float(hy)));
    lo[o2 + 1] = __halves2bfloat162(__float2bfloat16(x.z - __bfloat162float(hz)),
                                    __float2bfloat16(x.w - __bfloat162float(hw)));
}

// ---------------- MMA / cp.async helpers ------------------------------------
__device__ __forceinline__ void ldsm4(u32* r, const void* p) {
    u32 a = (u32)__cvta_generic_to_shared(p);
    asm volatile("ldmatrix.sync.aligned.m8n8.x4.shared.b16 {%0,%1,%2,%3}, [%4];"
                 : "=r"(r[0]), "=r"(r[1]), "=r"(r[2]), "=r"(r[3]) : "r"(a));
}
__device__ __forceinline__ void ldsm2t(u32* r, const void* p) {
    u32 a = (u32)__cvta_generic_to_shared(p);
    asm volatile("ldmatrix.sync.aligned.m8n8.x2.trans.shared.b16 {%0,%1}, [%2];"
                 : "=r"(r[0]), "=r"(r[1]) : "r"(a));
}
__device__ __forceinline__ void mma16816(float* d, const u32* a, const u32* b) {
    asm volatile("mma.sync.aligned.m16n8k16.row.col.f32.bf16.bf16.f32 "
                 "{%0,%1,%2,%3}, {%4,%5,%6,%7}, {%8,%9}, {%0,%1,%2,%3};"
                 : "+f"(d[0]), "+f"(d[1]), "+f"(d[2]), "+f"(d[3])
                 : "r"(a[0]), "r"(a[1]), "r"(a[2]), "r"(a[3]),
                   "r"(b[0]), "r"(b[1]));
}
__device__ __forceinline__ void cpa16(void* smem, const void* g, int sz) {
    u32 a = (u32)__cvta_generic_to_shared(smem);
    asm volatile("cp.async.cg.shared.global [%0], [%1], 16, %2;"
                 :: "r"(a), "l"(g), "r"(sz));
}
#define CP_COMMIT asm volatile("cp.async.commit_group;")
#define CP_WAIT1  asm volatile("cp.async.wait_group 1;")
#define CP_WAIT0  asm volatile("cp.async.wait_group 0;")

// ---------------- bf16x3 tensor-core GEMM (3-stage cp.async pipeline) -------
#define GBM 128
#define GBN 128
#define GBK 16
#define GSA 24
#define GSB 136
#define G_ASZ (GBM * GSA)                 // 3072 elems
#define G_BSZ (GBK * GSB)                 // 2176 elems
#define G_PSZ (2 * G_ASZ + 2 * G_BSZ)     // per-stage elems = 10496
#define GEMM_SMEM (3 * G_PSZ * 2)         // bytes = 62976

__global__ void __launch_bounds__(256, 2)
gemm_bf16x3_kernel(const __nv_bfloat16* __restrict__ Ahi,
                   const __nv_bfloat16* __restrict__ Alo,
                   const __nv_bfloat16* __restrict__ Bhi,
                   const __nv_bfloat16* __restrict__ Blo,
                   float* __restrict__ C, int M, int N, int K) {
    extern __shared__ __nv_bfloat16 smem[];

    int tid = threadIdx.x;
    int warp = tid >> 5;
    int lane = tid & 31;
    int wm = warp & 1;
    int wn = warp >> 1;
    int rowBase = blockIdx.y * GBM;
    int colBase = blockIdx.x * GBN;

    int aRow = tid >> 1;
    int aHalf = (tid & 1) * 8;
    int bRow = tid >> 4;
    int bCol = (tid & 15) * 8;

    int gr = rowBase + aRow;
    int aSz = (gr < M) ? 16 : 0;
    size_t aOff = (size_t)(gr < M ? gr : 0) * K + aHalf;
    size_t bOffBase = (size_t)bRow * N + colBase + bCol;

    float acc[4][4][4];
    #pragma unroll
    for (int i = 0; i < 4; i++) {
        #pragma unroll
        for (int j = 0; j < 4; j++) {
            #pragma unroll
            for (int k = 0; k < 4; k++) acc[i][j][k] = 0.f;
        }
    }

    int lrow = lane & 15;
    int lcol = (lane >> 4) * 8;
    int KT = K / GBK;

#define PF(stg, kt_) { \
    __nv_bfloat16* sb_ = smem + (stg) * G_PSZ; \
    int kk_ = (kt_) * GBK; \
    cpa16(sb_ + aRow * GSA + aHalf, Ahi + aOff + kk_, aSz); \
    cpa16(sb_ + G_ASZ + aRow * GSA + aHalf, Alo + aOff + kk_, aSz); \
    cpa16(sb_ + 2 * G_ASZ + bRow * GSB + bCol, Bhi + bOffBase + (size_t)kk_ * N, 16); \
    cpa16(sb_ + 2 * G_ASZ + G_BSZ + bRow * GSB + bCol, Blo + bOffBase + (size_t)kk_ * N, 16); \
    CP_COMMIT; }

    PF(0, 0);
    if (KT > 1) PF(1, 1);

    for (int kt = 0; kt < KT; kt++) {
        if (kt + 1 < KT) { CP_WAIT1; } else { CP_WAIT0; }
        __syncthreads();
        if (kt + 2 < KT) {
            int ns = (kt + 2) % 3;
            PF(ns, kt + 2);
        }
        __nv_bfloat16* sb = smem + (kt % 3) * G_PSZ;
        __nv_bfloat16* sAhi = sb;
        __nv_bfloat16* sAlo = sb + G_ASZ;
        __nv_bfloat16* sBhi = sb + 2 * G_ASZ;
        __nv_bfloat16* sBlo = sb + 2 * G_ASZ + G_BSZ;

        u32 fah[4][4];
        u32 fal[4][4];
        #pragma unroll
        for (int mt = 0; mt < 4; mt++) {
            ldsm4(fah[mt], sAhi + (wm * 64 + mt * 16 + lrow) * GSA + lcol);
            ldsm4(fal[mt], sAlo + (wm * 64 + mt * 16 + lrow) * GSA + lcol);
        }
        u32 fbh[4][2];
        u32 fbl[4][2];
        #pragma unroll
        for (int nt = 0; nt < 4; nt++) {
            ldsm2t(fbh[nt], sBhi + lrow * GSB + wn * 32 + nt * 8);
            ldsm2t(fbl[nt], sBlo + lrow * GSB + wn * 32 + nt * 8);
        }

        #pragma unroll
        for (int mt = 0; mt < 4; mt++) {
            #pragma unroll
            for (int nt = 0; nt < 4; nt++) {
                mma16816(acc[mt][nt], fah[mt], fbh[nt]);
                mma16816(acc[mt][nt], fah[mt], fbl[nt]);
                mma16816(acc[mt][nt], fal[mt], fbh[nt]);
            }
        }
    }
#undef PF

    #pragma unroll
    for (int mt = 0; mt < 4; mt++) {
        #pragma unroll
        for (int nt = 0; nt < 4; nt++) {
            int r0 = rowBase + wm * 64 + mt * 16 + (lane >> 2);
            int c = colBase + wn * 32 + nt * 8 + (lane & 3) * 2;
            if (r0 < M) {
                *(float2*)(C + (size_t)r0 * N + c) =
                    make_float2(acc[mt][nt][0], acc[mt][nt][1]);
            }
            if (r0 + 8 < M) {
                *(float2*)(C + (size_t)(r0 + 8) * N + c) =
                    make_float2(acc[mt][nt][2], acc[mt][nt][3]);
            }
        }
    }
}

// ---------------- fused online-softmax GAT aggregation (4 ILP chains) -------
// block = 128 threads, warp w = head w; one block per dst node v.
// fsd row layout: [fs(0..4D-1) | fd(0..4D-1)], row stride 8*D.
__global__ void __launch_bounds__(128)
gat_fused_kernel(const float* __restrict__ fsd, const float* __restrict__ attn,
                 const float* __restrict__ b, float* __restrict__ hout, int D) {
    __shared__ float sh[512];
    int v = blockIdx.x;
    int lane = threadIdx.x & 31;
    int w = threadIdx.x >> 5;
    int Ntot = 8 * D;
    int half = 4 * D;
    int e0 = g_rowptr[v], e1 = g_rowptr[v + 1];

    if (D == 128) {
        int off = w * 128 + lane * 4;
        float4 fdv = *(const float4*)(fsd + (size_t)v * Ntot + half + off);
        float4 aw = *(const float4*)(attn + off);
        float m0 = -INFINITY, m1 = -INFINITY, m2 = -INFINITY, m3 = -INFINITY;
        float s0 = 0.f, s1 = 0.f, s2 = 0.f, s3 = 0.f;
        float4 A0 = make_float4(0.f, 0.f, 0.f, 0.f);
        float4 A1 = A0, A2 = A0, A3 = A0;

        int e = e0;
        for (; e + 3 < e1; e += 4) {
            int i0 = g_csr_src[e];
            int i1 = g_csr_src[e + 1];
            int i2 = g_csr_src[e + 2];
            int i3 = g_csr_src[e + 3];
            float4 f0 = *(const float4*)(fsd + (size_t)i0 * Ntot + off);
            float4 f1 = *(const float4*)(fsd + (size_t)i1 * Ntot + off);
            float4 f2 = *(const float4*)(fsd + (size_t)i2 * Ntot + off);
            float4 f3 = *(const float4*)(fsd + (size_t)i3 * Ntot + off);
            float x;
            float p0 = 0.f, p1 = 0.f, p2 = 0.f, p3 = 0.f;
            x = f0.x + fdv.x; p0 += aw.x * (x > 0.f ? x : 0.2f * x);
            x = f0.y + fdv.y; p0 += aw.y * (x > 0.f ? x : 0.2f * x);
            x = f0.z + fdv.z; p0 += aw.z * (x > 0.f ? x : 0.2f * x);
            x = f0.w + fdv.w; p0 += aw.w * (x > 0.f ? x : 0.2f * x);
            x = f1.x + fdv.x; p1 += aw.x * (x > 0.f ? x : 0.2f * x);
            x = f1.y + fdv.y; p1 += aw.y * (x > 0.f ? x : 0.2f * x);
            x = f1.z + fdv.z; p1 += aw.z * (x > 0.f ? x : 0.2f * x);
            x = f1.w + fdv.w; p1 += aw.w * (x > 0.f ? x : 0.2f * x);
            x = f2.x + fdv.x; p2 += aw.x * (x > 0.f ? x : 0.2f * x);
            x = f2.y + fdv.y; p2 += aw.y * (x > 0.f ? x : 0.2f * x);
            x = f2.z + fdv.z; p2 += aw.z * (x > 0.f ? x : 0.2f * x);
            x = f2.w + fdv.w; p2 += aw.w * (x > 0.f ? x : 0.2f * x);
            x = f3.x + fdv.x; p3 += aw.x * (x > 0.f ? x : 0.2f * x);
            x = f3.y + fdv.y; p3 += aw.y * (x > 0.f ? x : 0.2f * x);
            x = f3.z + fdv.z; p3 += aw.z * (x > 0.f ? x : 0.2f * x);
            x = f3.w + fdv.w; p3 += aw.w * (x > 0.f ? x : 0.2f * x);
            #pragma unroll
            for (int o = 16; o; o >>= 1) {
                p0 += __shfl_xor_sync(0xffffffffu, p0, o);
                p1 += __shfl_xor_sync(0xffffffffu, p1, o);
                p2 += __shfl_xor_sync(0xffffffffu, p2, o);
                p3 += __shfl_xor_sync(0xffffffffu, p3, o);
            }
            if (p0 <= m0) {
                float q = __expf(p0 - m0);
                s0 += q; A0.x += q * f0.x; A0.y += q * f0.y; A0.z += q * f0.z; A0.w += q * f0.w;
            } else {
                float c = __expf(m0 - p0);
                s0 = s0 * c + 1.f;
                A0.x = A0.x * c + f0.x; A0.y = A0.y * c + f0.y;
                A0.z = A0.z * c + f0.z; A0.w = A0.w * c + f0.w;
                m0 = p0;
            }
            if (p1 <= m1) {
                float q = __expf(p1 - m1);
                s1 += q; A1.x += q * f1.x; A1.y += q * f1.y; A1.z += q * f1.z; A1.w += q * f1.w;
            } else {
                float c = __expf(m1 - p1);
                s1 = s1 * c + 1.f;
                A1.x = A1.x * c + f1.x; A1.y = A1.y * c + f1.y;
                A1.z = A1.z * c + f1.z; A1.w = A1.w * c + f1.w;
                m1 = p1;
            }
            if (p2 <= m2) {
                float q = __expf(p2 - m2);
                s2 += q; A2.x += q * f2.x; A2.y += q * f2.y; A2.z += q * f2.z; A2.w += q * f2.w;
            } else {
                float c = __expf(m2 - p2);
                s2 = s2 * c + 1.f;
                A2.x = A2.x * c + f2.x; A2.y = A2.y * c + f2.y;
                A2.z = A2.z * c + f2.z; A2.w = A2.w * c + f2.w;
                m2 = p2;
            }
            if (p3 <= m3) {
                float q = __expf(p3 - m3);
                s3 += q; A3.x += q * f3.x; A3.y += q * f3.y; A3.z += q * f3.z; A3.w += q * f3.w;
            } else {
                float c = __expf(m3 - p3);
                s3 = s3 * c + 1.f;
                A3.x = A3.x * c + f3.x; A3.y = A3.y * c + f3.y;
                A3.z = A3.z * c + f3.z; A3.w = A3.w * c + f3.w;
                m3 = p3;
            }
        }
        for (; e < e1; e++) {
            int i0 = g_csr_src[e];
            float4 f0 = *(const float4*)(fsd + (size_t)i0 * Ntot + off);
            float x, p0 = 0.f;
            x = f0.x + fdv.x; p0 += aw.x * (x > 0.f ? x : 0.2f * x);
            x = f0.y + fdv.y; p0 += aw.y * (x > 0.f ? x : 0.2f * x);
            x = f0.z + fdv.z; p0 += aw.z * (x > 0.f ? x : 0.2f * x);
            x = f0.w + fdv.w; p0 += aw.w * (x > 0.f ? x : 0.2f * x);
            #pragma unroll
            for (int o = 16; o; o >>= 1) p0 += __shfl_xor_sync(0xffffffffu, p0, o);
            if (p0 <= m0) {
                float q = __expf(p0 - m0);
                s0 += q; A0.x += q * f0.x; A0.y += q * f0.y; A0.z += q * f0.z; A0.w += q * f0.w;
            } else {
                float c = __expf(m0 - p0);
                s0 = s0 * c + 1.f;
                A0.x = A0.x * c + f0.x; A0.y = A0.y * c + f0.y;
                A0.z = A0.z * c + f0.z; A0.w = A0.w * c + f0.w;
                m0 = p0;
            }
        }
        // merge 4 chains
        float M = fmaxf(fmaxf(m0, m1), fmaxf(m2, m3));
        float q0 = (m0 > -INFINITY) ? __expf(m0 - M) : 0.f;
        float q1 = (m1 > -INFINITY) ? __expf(m1 - M) : 0.f;
        float q2 = (m2 > -INFINITY) ? __expf(m2 - M) : 0.f;
        float q3 = (m3 > -INFINITY) ? __expf(m3 - M) : 0.f;
        float ssum = s0 * q0 + s1 * q1 + s2 * q2 + s3 * q3;
        float inv = (e1 > e0) ? 1.f / ssum : 0.f;
        sh[off]     = (A0.x * q0 + A1.x * q1 + A2.x * q2 + A3.x * q3) * inv;
        sh[off + 1] = (A0.y * q0 + A1.y * q1 + A2.y * q2 + A3.y * q3) * inv;
        sh[off + 2] = (A0.z * q0 + A1.z * q1 + A2.z * q2 + A3.z * q3) * inv;
        sh[off + 3] = (A0.w * q0 + A1.w * q1 + A2.w * q2 + A3.w * q3) * inv;
    } else { // D == 64
        int off = w * 64 + lane * 2;
        float2 fdv = *(const float2*)(fsd + (size_t)v * Ntot + half + off);
        float2 aw = *(const float2*)(attn + off);
        float m0 = -INFINITY, m1 = -INFINITY;
        float s0 = 0.f, s1 = 0.f;
        float2 A0 = make_float2(0.f, 0.f);
        float2 A1 = A0;

        int e = e0;
        for (; e + 1 < e1; e += 2) {
            int i0 = g_csr_src[e];
            int i1 = g_csr_src[e + 1];
            float2 f0 = *(const float2*)(fsd + (size_t)i0 * Ntot + off);
            float2 f1 = *(const float2*)(fsd + (size_t)i1 * Ntot + off);
            float x;
            float p0 = 0.f, p1 = 0.f;
            x = f0.x + fdv.x; p0 += aw.x * (x > 0.f ? x : 0.2f * x);
            x = f0.y + fdv.y; p0 += aw.y * (x > 0.f ? x : 0.2f * x);
            x = f1.x + fdv.x; p1 += aw.x * (x > 0.f ? x : 0.2f * x);
            x = f1.y + fdv.y; p1 += aw.y * (x > 0.f ? x : 0.2f * x);
            #pragma unroll
            for (int o = 16; o; o >>= 1) {
                p0 += __shfl_xor_sync(0xffffffffu, p0, o);
                p1 += __shfl_xor_sync(0xffffffffu, p1, o);
            }
            if (p0 <= m0) {
                float q = __expf(p0 - m0);
                s0 += q; A0.x += q * f0.x; A0.y += q * f0.y;
            } else {
                float c = __expf(m0 - p0);
                s0 = s0 * c + 1.f;
                A0.x = A0.x * c + f0.x; A0.y = A0.y * c + f0.y;
                m0 = p0;
            }
            if (p1 <= m1) {
                float q = __expf(p1 - m1);
                s1 += q; A1.x += q * f1.x; A1.y += q * f1.y;
            } else {
                float c = __expf(m1 - p1);
                s1 = s1 * c + 1.f;
                A1.x = A1.x * c + f1.x; A1.y = A1.y * c + f1.y;
                m1 = p1;
            }
        }
        for (; e < e1; e++) {
            int i0 = g_csr_src[e];
            float2 f0 = *(const float2*)(fsd + (size_t)i0 * Ntot + off);
            float x, p0 = 0.f;
            x = f0.x + fdv.x; p0 += aw.x * (x > 0.f ? x : 0.2f * x);
            x = f0.y + fdv.y; p0 += aw.y * (x > 0.f ? x : 0.2f * x);
            #pragma unroll
            for (int o = 16; o; o >>= 1) p0 += __shfl_xor_sync(0xffffffffu, p0, o);
            if (p0 <= m0) {
                float q = __expf(p0 - m0);
                s0 += q; A0.x += q * f0.x; A0.y += q * f0.y;
            } else {
                float c = __expf(m0 - p0);
                s0 = s0 * c + 1.f;
                A0.x = A0.x * c + f0.x; A0.y = A0.y * c + f0.y;
                m0 = p0;
            }
        }
        float M = fmaxf(m0, m1);
        float q0 = (m0 > -INFINITY) ? __expf(m0 - M) : 0.f;
        float q1 = (m1 > -INFINITY) ? __expf(m1 - M) : 0.f;
        float ssum = s0 * q0 + s1 * q1;
        float inv = (e1 > e0) ? 1.f / ssum : 0.f;
        sh[off]     = (A0.x * q0 + A1.x * q1) * inv;
        sh[off + 1] = (A0.y * q0 + A1.y * q1) * inv;
    }
    __syncthreads();

    if (threadIdx.x < D) {
        int t = threadIdx.x;
        float m = 0.f;
        #pragma unroll
        for (int h = 0; h < 4; h++) m += sh[h * D + t] + b[h * D + t];
        m *= 0.25f;
        hout[(size_t)v * D + t] = (m > 0.f) ? m : 0.01f * m;
    }
}

// ---------------- final node-mean readout -----------------------------------
__global__ void node_mean_kernel(const float* __restrict__ hin,
                                 float* __restrict__ out, int n, int D) {
    int d = blockIdx.x;
    float s = 0.f;
    for (int v = threadIdx.x; v < n; v += blockDim.x)
        s += hin[(size_t)v * D + d];
    __shared__ float red[256];
    red[threadIdx.x] = s;
    __syncthreads();
    for (int o = 128; o; o >>= 1) {
        if (threadIdx.x < o) red[threadIdx.x] += red[threadIdx.x + o];
        __syncthreads();
    }
    if (threadIdx.x == 0) out[d] = red[0] / (float)n;
}

// ---------------- launch ----------------------------------------------------
extern "C" void kernel_launch(void* const* d_in, const int* in_sizes, int n_in,
                              void* d_out, int out_size) {
    const float* n_feat = (const float*)d_in[0];
    const int*   src    = (const int*)d_in[1];
    const int*   dst    = (const int*)d_in[2];
    const float* Wl0 = (const float*)d_in[3];
    const float* Wr0 = (const float*)d_in[4];
    const float* attn0 = (const float*)d_in[5];
    const float* b0 = (const float*)d_in[6];
    const float* Wl1 = (const float*)d_in[7];
    const float* Wr1 = (const float*)d_in[8];
    const float* attn1 = (const float*)d_in[9];
    const float* b1 = (const float*)d_in[10];
    const float* Wl2 = (const float*)d_in[11];
    const float* Wr2 = (const float*)d_in[12];
    const float* attn2 = (const float*)d_in[13];
    const float* b2 = (const float*)d_in[14];
    float* out = (float*)d_out;

    int n = in_sizes[0] / 512;   // 20000
    int E = in_sizes[1];         // 320000

    float* fsd;
    float* hin;
    __nv_bfloat16* ahi;
    __nv_bfloat16* alo;
    __nv_bfloat16* bhi;
    __nv_bfloat16* blo;
    cudaGetSymbolAddress((void**)&fsd, g_fsd);
    cudaGetSymbolAddress((void**)&hin, g_hin);
    cudaGetSymbolAddress((void**)&ahi, g_ahi);
    cudaGetSymbolAddress((void**)&alo, g_alo);
    cudaGetSymbolAddress((void**)&bhi, g_bhi);
    cudaGetSymbolAddress((void**)&blo, g_blo);

    cudaFuncSetAttribute(gemm_bf16x3_kernel,
                         cudaFuncAttributeMaxDynamicSharedMemorySize, GEMM_SMEM);

    // CSR by dst
    zero_deg_kernel<<<(n + 255) / 256, 256>>>(n);
    hist_dst_kernel<<<(E + 255) / 256, 256>>>(dst, E);
    scan_exclusive_kernel<<<1, 1024>>>(n);
    scatter_csr_kernel<<<(E + 255) / 256, 256>>>(src, dst, E);

    int mtiles = (n + 127) / 128;

    // ---- layer 0: 512 -> 4x128 (merged Wl|Wr GEMM, N=1024)
    split_bf16_kernel<<<(n * 512 / 4 + 255) / 256, 256>>>(
        (const float4*)n_feat, (__nv_bfloat162*)ahi, (__nv_bfloat162*)alo, n * 512 / 4);
    split_w_kernel<<<(512 * 512 / 4 + 255) / 256, 256>>>(
        (const float4*)Wl0, (__nv_bfloat162*)bhi, (__nv_bfloat162*)blo,
        512 * 512 / 4, 512, 1024, 0);
    split_w_kernel<<<(512 * 512 / 4 + 255) / 256, 256>>>(
        (const float4*)Wr0, (__nv_bfloat162*)bhi, (__nv_bfloat162*)blo,
        512 * 512 / 4, 512, 1024, 512);
    gemm_bf16x3_kernel<<<dim3(8, mtiles), 256, GEMM_SMEM>>>(ahi, alo, bhi, blo, fsd, n, 1024, 512);
    gat_fused_kernel<<<n, 128>>>(fsd, attn0, b0, hin, 128);

    // ---- layer 1: 128 -> 4x128
    split_bf16_kernel<<<(n * 128 / 4 + 255) / 256, 256>>>(
        (const float4*)hin, (__nv_bfloat162*)ahi, (__nv_bfloat162*)alo, n * 128 / 4);
    split_w_kernel<<<(128 * 512 / 4 + 255) / 256, 256>>>(
        (const float4*)Wl1, (__nv_bfloat162*)bhi, (__nv_bfloat162*)blo,
        128 * 512 / 4, 512, 1024, 0);
    split_w_kernel<<<(128 * 512 / 4 + 255) / 256, 256>>>(
        (const float4*)Wr1, (__nv_bfloat162*)bhi, (__nv_bfloat162*)blo,
        128 * 512 / 4, 512, 1024, 512);
    gemm_bf16x3_kernel<<<dim3(8, mtiles), 256, GEMM_SMEM>>>(ahi, alo, bhi, blo, fsd, n, 1024, 128);
    gat_fused_kernel<<<n, 128>>>(fsd, attn1, b1, hin, 128);

    // ---- layer 2: 128 -> 4x64
    split_bf16_kernel<<<(n * 128 / 4 + 255) / 256, 256>>>(
        (const float4*)hin, (__nv_bfloat162*)ahi, (__nv_bfloat162*)alo, n * 128 / 4);
    split_w_kernel<<<(128 * 256 / 4 + 255) / 256, 256>>>(
        (const float4*)Wl2, (__nv_bfloat162*)bhi, (__nv_bfloat162*)blo,
        128 * 256 / 4, 256, 512, 0);
    split_w_kernel<<<(128 * 256 / 4 + 255) / 256, 256>>>(
        (const float4*)Wr2, (__nv_bfloat162*)bhi, (__nv_bfloat162*)blo,
        128 * 256 / 4, 256, 512, 256);
    gemm_bf16x3_kernel<<<dim3(4, mtiles), 256, GEMM_SMEM>>>(ahi, alo, bhi, blo, fsd, n, 512, 128);
    gat_fused_kernel<<<n, 128>>>(fsd, attn2, b2, hin, 64);

    node_mean_kernel<<<64, 256>>>(hin, out, n, 64);
}